// round 16
// baseline (speedup 1.0000x reference)
#include <cuda_runtime.h>
#include <cuda_fp16.h>
#include <math.h>
#include <stdint.h>

#define BATCH 2
#define SEQ   2048
#define DIM   2048
#define NH    16
#define DH    128

// scale * log2(e): QK scores come out pre-scaled for exp2.
#define QSCALE (0.08838834764831845f * 1.4426950408889634f)

// Scratch — __device__ globals per allocation rules.
__device__ __half g_hI0[BATCH * SEQ * DIM];
__device__ __half g_hI1[BATCH * SEQ * DIM];
__device__ __half g_hI2[BATCH * SEQ * DIM];
__device__ __half g_hQ[BATCH * SEQ * DIM];
__device__ __half g_hK[BATCH * SEQ * DIM];
__device__ __half g_hV[BATCH * SEQ * DIM];
__device__ __half g_hO[BATCH * SEQ * DIM];
__device__ __half g_hW0[DIM * DIM];
__device__ __half g_hW1[DIM * DIM];
__device__ __half g_hW2[DIM * DIM];
__device__ __half g_hW3[DIM * DIM];

// ===========================================================================
// Helpers
// ===========================================================================
__device__ __forceinline__ uint32_t smem_u32(const void* p) {
    uint32_t a;
    asm("{ .reg .u64 t; cvta.to.shared.u64 t, %1; cvt.u32.u64 %0, t; }"
        : "=r"(a) : "l"(p));
    return a;
}

__device__ __forceinline__ void ldsm_x4(uint32_t addr, uint32_t r[4]) {
    asm volatile("ldmatrix.sync.aligned.m8n8.x4.shared.b16 {%0,%1,%2,%3}, [%4];"
                 : "=r"(r[0]), "=r"(r[1]), "=r"(r[2]), "=r"(r[3]) : "r"(addr));
}
__device__ __forceinline__ void ldsm_x4_t(uint32_t addr, uint32_t r[4]) {
    asm volatile("ldmatrix.sync.aligned.m8n8.x4.trans.shared.b16 {%0,%1,%2,%3}, [%4];"
                 : "=r"(r[0]), "=r"(r[1]), "=r"(r[2]), "=r"(r[3]) : "r"(addr));
}

__device__ __forceinline__ void mma_f16(float c[4], const uint32_t a[4],
                                        const uint32_t b0, const uint32_t b1) {
    asm volatile(
        "mma.sync.aligned.m16n8k16.row.col.f32.f16.f16.f32 "
        "{%0,%1,%2,%3}, {%4,%5,%6,%7}, {%8,%9}, {%0,%1,%2,%3};"
        : "+f"(c[0]), "+f"(c[1]), "+f"(c[2]), "+f"(c[3])
        : "r"(a[0]), "r"(a[1]), "r"(a[2]), "r"(a[3]), "r"(b0), "r"(b1));
}

__device__ __forceinline__ void cp16(uint32_t saddr, const void* gaddr) {
    asm volatile("cp.async.cg.shared.global [%0], [%1], 16;"
                 :: "r"(saddr), "l"(gaddr));
}
#define CP_COMMIT() asm volatile("cp.async.commit_group;" ::: "memory")
#define CP_WAIT(n)  asm volatile("cp.async.wait_group %0;" :: "n"(n) : "memory")

__device__ __forceinline__ uint32_t h2pack(float a, float b) {
    __half2 h = __floats2half2_rn(a, b);
    return *(uint32_t*)&h;
}

// ===========================================================================
// Conversion: fp32 -> fp16 (rn), 7 tensors in one launch.
// ===========================================================================
__global__ __launch_bounds__(256) void cvt7_kernel(
    const float* __restrict__ i0, const float* __restrict__ i1,
    const float* __restrict__ i2, const float* __restrict__ i3,
    const float* __restrict__ i4, const float* __restrict__ i5,
    const float* __restrict__ i6,
    __half* __restrict__ o0, __half* __restrict__ o1,
    __half* __restrict__ o2, __half* __restrict__ o3,
    __half* __restrict__ o4, __half* __restrict__ o5,
    __half* __restrict__ o6,
    int n4x, int n4w)
{
    const int z = blockIdx.z;
    const int n4 = (z < 3) ? n4x : n4w;
    int i = blockIdx.x * blockDim.x + threadIdx.x;
    if (i >= n4) return;
    const float* in;
    __half* out;
    switch (z) {
        case 0: in = i0; out = o0; break;
        case 1: in = i1; out = o1; break;
        case 2: in = i2; out = o2; break;
        case 3: in = i3; out = o3; break;
        case 4: in = i4; out = o4; break;
        case 5: in = i5; out = o5; break;
        default: in = i6; out = o6; break;
    }
    float4 v = ((const float4*)in)[i];
    uint2 o;
    o.x = h2pack(v.x, v.y);
    o.y = h2pack(v.z, v.w);
    ((uint2*)out)[i] = o;
}

// ===========================================================================
// fp16 HMMA GEMM — R12 mainloop (measured best). Epilogue gains per-z output
// scale (used to fold attention scale*log2e into the Q projection).
// ===========================================================================
#define GRS    40
#define GTILE  (128 * GRS * 2)
#define GSTAGE (2 * GTILE)
#define NSTG   3
#define GEMM_SMEM (NSTG * GSTAGE)       // 61440 B

__global__ __launch_bounds__(128, 2) void gemm_f16_kernel(
    const __half* __restrict__ A0, const __half* __restrict__ A1,
    const __half* __restrict__ A2,
    const __half* __restrict__ W0, const __half* __restrict__ W1,
    const __half* __restrict__ W2,
    const float* __restrict__ b0, const float* __restrict__ b1,
    const float* __restrict__ b2,
    float* __restrict__ Cf,
    __half* __restrict__ H0, __half* __restrict__ H1, __half* __restrict__ H2,
    int outhalf, float s0, float s1, float s2, int M, int N, int Kd)
{
    extern __shared__ char smem[];
    const uint32_t sbase = smem_u32(smem);
    const int z = blockIdx.z;
    const __half* Ah   = (z == 0) ? A0 : (z == 1) ? A1 : A2;
    const __half* Wh   = (z == 0) ? W0 : (z == 1) ? W1 : W2;
    const float*  bias = (z == 0) ? b0 : (z == 1) ? b1 : b2;
    __half*       Ch   = (z == 0) ? H0 : (z == 1) ? H1 : H2;
    const float   osc  = (z == 0) ? s0 : (z == 1) ? s1 : s2;

    const int tid  = threadIdx.x;
    const int wid  = tid >> 5;
    const int lane = tid & 31;
    const int wm   = wid >> 1;
    const int wn   = wid & 1;
    const int bm   = blockIdx.y * 128;
    const int bn   = blockIdx.x * 128;

    float acc[4][8][4];
    #pragma unroll
    for (int i = 0; i < 4; i++)
        #pragma unroll
        for (int j = 0; j < 8; j++)
            #pragma unroll
            for (int e = 0; e < 4; e++) acc[i][j][e] = 0.f;

    const int crow = tid >> 2;
    const int ccol = tid & 3;

#define ISSUE_STAGE(CH, STG) do {                                             \
    const int k0_ = (CH) * 32;                                                \
    const uint32_t sb_ = sbase + (STG) * GSTAGE;                              \
    _Pragma("unroll")                                                         \
    for (int t = 0; t < 4; t++) {                                             \
        const int row_ = crow + t * 32;                                       \
        const uint32_t so_ = (uint32_t)(row_ * 80 + ccol * 16);               \
        cp16(sb_ + so_,         Ah + (size_t)(bm + row_) * Kd + k0_ + ccol * 8); \
        cp16(sb_ + GTILE + so_, Wh + (size_t)(bn + row_) * Kd + k0_ + ccol * 8); \
    }                                                                         \
} while (0)

    #pragma unroll
    for (int s = 0; s < NSTG; s++) { ISSUE_STAGE(s, s); CP_COMMIT(); }

    const int g  = lane >> 3;
    const int r8 = lane & 7;
    const int nchunk = Kd / 32;

    for (int ch = 0; ch < nchunk; ch++) {
        CP_WAIT(NSTG - 1);
        __syncthreads();
        const uint32_t buf = sbase + (ch % NSTG) * GSTAGE;

        #pragma unroll
        for (int ks = 0; ks < 2; ks++) {
            const int k0 = ks * 16;
            uint32_t af[4][4];
            #pragma unroll
            for (int mt = 0; mt < 4; mt++) {
                int row = wm * 64 + mt * 16 + r8 + (g & 1) * 8;
                uint32_t off = (uint32_t)(row * GRS + k0 + (g >> 1) * 8) * 2;
                ldsm_x4(buf + off, af[mt]);
            }
            uint32_t bf[4][4];
            #pragma unroll
            for (int np = 0; np < 4; np++) {
                int nrow = wn * 64 + np * 16 + r8 + (g >> 1) * 8;
                uint32_t off = (uint32_t)(nrow * GRS + k0 + (g & 1) * 8) * 2;
                ldsm_x4(buf + GTILE + off, bf[np]);
            }
            #pragma unroll
            for (int mt = 0; mt < 4; mt++) {
                #pragma unroll
                for (int nt = 0; nt < 8; nt++) {
                    const int np = nt >> 1, hf = (nt & 1) * 2;
                    mma_f16(acc[mt][nt], af[mt], bf[np][hf], bf[np][hf + 1]);
                }
            }
        }
        __syncthreads();
        if (ch + NSTG < nchunk) ISSUE_STAGE(ch + NSTG, ch % NSTG);
        CP_COMMIT();
    }

    // Epilogue: (acc + bias) * osc.
    #pragma unroll
    for (int nt = 0; nt < 8; nt++) {
        const int gcol = bn + wn * 64 + nt * 8 + (lane & 3) * 2;
        const float2 bv = *(const float2*)&bias[gcol];
        #pragma unroll
        for (int mt = 0; mt < 4; mt++) {
            const int grow = bm + wm * 64 + mt * 16 + (lane >> 2);
            float x0 = (acc[mt][nt][0] + bv.x) * osc;
            float y0 = (acc[mt][nt][1] + bv.y) * osc;
            float x1 = (acc[mt][nt][2] + bv.x) * osc;
            float y1 = (acc[mt][nt][3] + bv.y) * osc;
            if (outhalf) {
                *(uint32_t*)&Ch[(size_t)grow * N + gcol] = h2pack(x0, y0);
                *(uint32_t*)&Ch[(size_t)(grow + 8) * N + gcol] = h2pack(x1, y1);
            } else {
                float2 o0 = {x0, y0}, o1 = {x1, y1};
                *(float2*)&Cf[(size_t)grow * N + gcol] = o0;
                *(float2*)&Cf[(size_t)(grow + 8) * N + gcol] = o1;
            }
        }
    }
#undef ISSUE_STAGE
}

// ===========================================================================
// Flash attention, fp16 HMMA, P-in-registers. Log2-domain softmax:
// Q pre-scaled by scale*log2e, so p = exp2(c - m), cor = exp2(m_old - m_new).
// Causal mask applied under a warp-uniform branch.
// ===========================================================================
#define VRS     136
#define FT_TILE (64 * VRS * 2)
#define FSM_KV0 FT_TILE
#define FLASH_SMEM (FT_TILE * 5)        // 87040 B

__global__ __launch_bounds__(128, 1) void flash_hmma_kernel(
    const __half* __restrict__ Q, const __half* __restrict__ K,
    const __half* __restrict__ V, const int* __restrict__ causal_ptr,
    __half* __restrict__ O)
{
    extern __shared__ char smem[];
    const uint32_t sb = smem_u32(smem);
    const int tid  = threadIdx.x;
    const int lane = tid & 31;
    const int wq   = tid >> 5;
    const int qt   = blockIdx.x;
    const int h    = blockIdx.y;
    const int b    = blockIdx.z;
    const int q0   = qt * 64;
    const size_t base = (size_t)b * SEQ * DIM + (size_t)h * DH;
    const int causal = *causal_ptr;
    const int nkt = causal ? (qt + 1) : (SEQ / 64);

    const int g  = lane >> 3;
    const int r8 = lane & 7;
    const int r  = lane >> 2;
    const int cc = (lane & 3) * 2;

#define ISSUE_KV(KT, STG) do {                                                \
    const int kk0_ = (KT) * 64;                                               \
    const uint32_t tb_ = sb + FSM_KV0 + (STG) * 2 * FT_TILE;                  \
    _Pragma("unroll")                                                         \
    for (int t = 0; t < 8; t++) {                                             \
        int idx = tid + t * 128;                                              \
        int row = idx >> 4, c = idx & 15;                                     \
        cp16(tb_ + row * 272 + c * 16,                                        \
             K + base + (size_t)(kk0_ + row) * DIM + c * 8);                  \
        cp16(tb_ + FT_TILE + row * 272 + c * 16,                              \
             V + base + (size_t)(kk0_ + row) * DIM + c * 8);                  \
    }                                                                         \
} while (0)

    #pragma unroll
    for (int t = 0; t < 8; t++) {
        int idx = tid + t * 128;
        int row = idx >> 4, c = idx & 15;
        cp16(sb + row * 272 + c * 16,
             Q + base + (size_t)(q0 + row) * DIM + c * 8);
    }
    ISSUE_KV(0, 0);
    CP_COMMIT();
    ISSUE_KV((1 < nkt ? 1 : nkt - 1), 1);
    CP_COMMIT();

    float m0 = -INFINITY, m1 = -INFINITY, l0 = 0.f, l1 = 0.f;
    float o[16][4];
    #pragma unroll
    for (int u = 0; u < 16; u++)
        #pragma unroll
        for (int e = 0; e < 4; e++) o[u][e] = 0.f;

    uint32_t aq[8][4];

    for (int kt = 0; kt < nkt; kt++) {
        CP_WAIT(1);
        __syncthreads();

        if (kt == 0) {
            #pragma unroll
            for (int ds = 0; ds < 8; ds++) {
                uint32_t addr = sb + (uint32_t)(wq * 16 + r8 + (g & 1) * 8) * 272
                              + (uint32_t)(ds * 16 + (g >> 1) * 8) * 2;
                ldsm_x4(addr, aq[ds]);
            }
        }

        const uint32_t kbuf = sb + FSM_KV0 + (uint32_t)(kt & 1) * 2 * FT_TILE;
        const uint32_t vbuf = kbuf + FT_TILE;

        float c[8][4];
        #pragma unroll
        for (int nt = 0; nt < 8; nt++)
            #pragma unroll
            for (int e = 0; e < 4; e++) c[nt][e] = 0.f;

        #pragma unroll
        for (int ds = 0; ds < 8; ds++) {
            uint32_t bf[4][4];
            #pragma unroll
            for (int j = 0; j < 4; j++) {
                uint32_t addr = kbuf + (uint32_t)(j * 16 + r8 + (g >> 1) * 8) * 272
                              + (uint32_t)(ds * 16 + (g & 1) * 8) * 2;
                ldsm_x4(addr, bf[j]);
            }
            #pragma unroll
            for (int nt = 0; nt < 8; nt++)
                mma_f16(c[nt], aq[ds], bf[nt >> 1][(nt & 1) * 2],
                        bf[nt >> 1][(nt & 1) * 2 + 1]);
        }

        // Causal mask, warp-uniform branch (scores already scaled in Q).
        if (causal && (kt == qt)) {
            const int qrow0 = q0 + wq * 16 + r;
            #pragma unroll
            for (int nt = 0; nt < 8; nt++) {
                #pragma unroll
                for (int e = 0; e < 4; e++) {
                    int key = kt * 64 + nt * 8 + cc + (e & 1);
                    int qr  = qrow0 + ((e >> 1) << 3);
                    if (key > qr) c[nt][e] = -INFINITY;
                }
            }
        }

        float mx0 = -INFINITY, mx1 = -INFINITY;
        #pragma unroll
        for (int nt = 0; nt < 8; nt++) {
            mx0 = fmaxf(mx0, fmaxf(c[nt][0], c[nt][1]));
            mx1 = fmaxf(mx1, fmaxf(c[nt][2], c[nt][3]));
        }
        mx0 = fmaxf(mx0, __shfl_xor_sync(0xffffffffu, mx0, 1));
        mx0 = fmaxf(mx0, __shfl_xor_sync(0xffffffffu, mx0, 2));
        mx1 = fmaxf(mx1, __shfl_xor_sync(0xffffffffu, mx1, 1));
        mx1 = fmaxf(mx1, __shfl_xor_sync(0xffffffffu, mx1, 2));
        const float nm0 = fmaxf(m0, mx0), nm1 = fmaxf(m1, mx1);
        const float cor0 = exp2f(m0 - nm0), cor1 = exp2f(m1 - nm1);

        uint32_t ph[8][2];
        float rs0 = 0.f, rs1 = 0.f;
        #pragma unroll
        for (int nt = 0; nt < 8; nt++) {
            float p0 = exp2f(c[nt][0] - nm0);
            float p1 = exp2f(c[nt][1] - nm0);
            float p2 = exp2f(c[nt][2] - nm1);
            float p3 = exp2f(c[nt][3] - nm1);
            rs0 += p0 + p1; rs1 += p2 + p3;
            ph[nt][0] = h2pack(p0, p1);
            ph[nt][1] = h2pack(p2, p3);
        }
        rs0 += __shfl_xor_sync(0xffffffffu, rs0, 1);
        rs0 += __shfl_xor_sync(0xffffffffu, rs0, 2);
        rs1 += __shfl_xor_sync(0xffffffffu, rs1, 1);
        rs1 += __shfl_xor_sync(0xffffffffu, rs1, 2);
        l0 = l0 * cor0 + rs0;
        l1 = l1 * cor1 + rs1;
        m0 = nm0; m1 = nm1;

        #pragma unroll
        for (int u = 0; u < 16; u++) {
            o[u][0] *= cor0; o[u][1] *= cor0;
            o[u][2] *= cor1; o[u][3] *= cor1;
        }

        #pragma unroll
        for (int kk = 0; kk < 4; kk++) {
            uint32_t pa[4] = { ph[2 * kk][0], ph[2 * kk][1],
                               ph[2 * kk + 1][0], ph[2 * kk + 1][1] };
            #pragma unroll
            for (int u = 0; u < 8; u++) {
                uint32_t bv[4];
                uint32_t addr = vbuf + (uint32_t)(kk * 16 + (lane & 15)) * 272
                              + (uint32_t)(u * 16 + (lane >> 4) * 8) * 2;
                ldsm_x4_t(addr, bv);
                mma_f16(o[2 * u],     pa, bv[0], bv[1]);
                mma_f16(o[2 * u + 1], pa, bv[2], bv[3]);
            }
        }

        __syncthreads();
        {
            int nx = kt + 2;
            if (nx >= nkt) nx = nkt - 1;
            ISSUE_KV(nx, kt & 1);
        }
        CP_COMMIT();
    }

    const float inv0 = 1.f / l0, inv1 = 1.f / l1;
    const int row0 = q0 + wq * 16 + r;
    #pragma unroll
    for (int u = 0; u < 16; u++) {
        int col = u * 8 + cc;
        *(uint32_t*)&O[base + (size_t)row0 * DIM + col] =
            h2pack(o[u][0] * inv0, o[u][1] * inv0);
        *(uint32_t*)&O[base + (size_t)(row0 + 8) * DIM + col] =
            h2pack(o[u][2] * inv1, o[u][3] * inv1);
    }
#undef ISSUE_KV
}

// ===========================================================================
extern "C" void kernel_launch(void* const* d_in, const int* in_sizes, int n_in,
                              void* d_out, int out_size)
{
    const float* q      = (const float*)d_in[0];
    const float* k      = (const float*)d_in[1];
    const float* v      = (const float*)d_in[2];
    const float* Wq     = (const float*)d_in[3];
    const float* bq     = (const float*)d_in[4];
    const float* Wk     = (const float*)d_in[5];
    const float* bk     = (const float*)d_in[6];
    const float* Wv     = (const float*)d_in[7];
    const float* bv     = (const float*)d_in[8];
    const float* Wo     = (const float*)d_in[9];
    const float* bo     = (const float*)d_in[10];
    const int*   causal = (const int*)d_in[11];
    float* out = (float*)d_out;

    __half *hI0, *hI1, *hI2, *hQ, *hK, *hV, *hO, *hW0, *hW1, *hW2, *hW3;
    cudaGetSymbolAddress((void**)&hI0, g_hI0);
    cudaGetSymbolAddress((void**)&hI1, g_hI1);
    cudaGetSymbolAddress((void**)&hI2, g_hI2);
    cudaGetSymbolAddress((void**)&hQ,  g_hQ);
    cudaGetSymbolAddress((void**)&hK,  g_hK);
    cudaGetSymbolAddress((void**)&hV,  g_hV);
    cudaGetSymbolAddress((void**)&hO,  g_hO);
    cudaGetSymbolAddress((void**)&hW0, g_hW0);
    cudaGetSymbolAddress((void**)&hW1, g_hW1);
    cudaGetSymbolAddress((void**)&hW2, g_hW2);
    cudaGetSymbolAddress((void**)&hW3, g_hW3);

    const int M = BATCH * SEQ;                   // 4096
    const int n4x = M * DIM / 4;
    const int n4w = DIM * DIM / 4;

    cudaFuncSetAttribute(gemm_f16_kernel,
                         cudaFuncAttributeMaxDynamicSharedMemorySize, GEMM_SMEM);
    cudaFuncSetAttribute(flash_hmma_kernel,
                         cudaFuncAttributeMaxDynamicSharedMemorySize, FLASH_SMEM);

    // All seven fp32->fp16 conversions in one launch.
    {
        dim3 cg(n4x / 256, 1, 7);
        cvt7_kernel<<<cg, 256>>>(q, k, v, Wq, Wk, Wv, Wo,
                                 hI0, hI1, hI2, hW0, hW1, hW2, hW3,
                                 n4x, n4w);
    }

    // Three projections in one launch; Q output pre-scaled by scale*log2e.
    {
        dim3 gg(DIM / 128, M / 128, 3);
        gemm_f16_kernel<<<gg, 128, GEMM_SMEM>>>(
            hI0, hI1, hI2, hW0, hW1, hW2, bq, bk, bv,
            nullptr, hQ, hK, hV, 1, QSCALE, 1.0f, 1.0f, M, DIM, DIM);
    }

    // Attention (log2-domain softmax).
    {
        dim3 fg(SEQ / 64, NH, BATCH);
        flash_hmma_kernel<<<fg, 128, FLASH_SMEM>>>(hQ, hK, hV, causal, hO);
    }

    // Output projection (fp32 out, unit scale).
    {
        dim3 gg(DIM / 128, M / 128, 1);
        gemm_f16_kernel<<<gg, 128, GEMM_SMEM>>>(
            hO, hO, hO, hW3, hW3, hW3, bo, bo, bo,
            out, nullptr, nullptr, nullptr, 0, 1.0f, 1.0f, 1.0f, M, DIM, DIM);
    }
}

// round 17
// speedup vs baseline: 1.0214x; 1.0214x over previous
#include <cuda_runtime.h>
#include <cuda_fp16.h>
#include <math.h>
#include <stdint.h>

#define BATCH 2
#define SEQ   2048
#define DIM   2048
#define NH    16
#define DH    128

// scale * log2(e): QK scores come out pre-scaled for exp2.
#define QSCALE (0.08838834764831845f * 1.4426950408889634f)

// Scratch — __device__ globals per allocation rules.
__device__ __half g_hI0[BATCH * SEQ * DIM];
__device__ __half g_hI1[BATCH * SEQ * DIM];
__device__ __half g_hI2[BATCH * SEQ * DIM];
__device__ __half g_hQ[BATCH * SEQ * DIM];
__device__ __half g_hK[BATCH * SEQ * DIM];
__device__ __half g_hV[BATCH * SEQ * DIM];
__device__ __half g_hO[BATCH * SEQ * DIM];
__device__ __half g_hW0[DIM * DIM];
__device__ __half g_hW1[DIM * DIM];
__device__ __half g_hW2[DIM * DIM];
__device__ __half g_hW3[DIM * DIM];

// ===========================================================================
// Helpers
// ===========================================================================
__device__ __forceinline__ uint32_t smem_u32(const void* p) {
    uint32_t a;
    asm("{ .reg .u64 t; cvta.to.shared.u64 t, %1; cvt.u32.u64 %0, t; }"
        : "=r"(a) : "l"(p));
    return a;
}

__device__ __forceinline__ void ldsm_x4(uint32_t addr, uint32_t r[4]) {
    asm volatile("ldmatrix.sync.aligned.m8n8.x4.shared.b16 {%0,%1,%2,%3}, [%4];"
                 : "=r"(r[0]), "=r"(r[1]), "=r"(r[2]), "=r"(r[3]) : "r"(addr));
}
__device__ __forceinline__ void ldsm_x4_t(uint32_t addr, uint32_t r[4]) {
    asm volatile("ldmatrix.sync.aligned.m8n8.x4.trans.shared.b16 {%0,%1,%2,%3}, [%4];"
                 : "=r"(r[0]), "=r"(r[1]), "=r"(r[2]), "=r"(r[3]) : "r"(addr));
}

__device__ __forceinline__ void mma_f16(float c[4], const uint32_t a[4],
                                        const uint32_t b0, const uint32_t b1) {
    asm volatile(
        "mma.sync.aligned.m16n8k16.row.col.f32.f16.f16.f32 "
        "{%0,%1,%2,%3}, {%4,%5,%6,%7}, {%8,%9}, {%0,%1,%2,%3};"
        : "+f"(c[0]), "+f"(c[1]), "+f"(c[2]), "+f"(c[3])
        : "r"(a[0]), "r"(a[1]), "r"(a[2]), "r"(a[3]), "r"(b0), "r"(b1));
}

__device__ __forceinline__ void cp16(uint32_t saddr, const void* gaddr) {
    asm volatile("cp.async.ca.shared.global [%0], [%1], 16;"
                 :: "r"(saddr), "l"(gaddr));
}
#define CP_COMMIT() asm volatile("cp.async.commit_group;" ::: "memory")
#define CP_WAIT(n)  asm volatile("cp.async.wait_group %0;" :: "n"(n) : "memory")

__device__ __forceinline__ uint32_t h2pack(float a, float b) {
    __half2 h = __floats2half2_rn(a, b);
    return *(uint32_t*)&h;
}

// ===========================================================================
// Conversion: fp32 -> fp16 (rn), 7 tensors in one launch.
// ===========================================================================
__global__ __launch_bounds__(256) void cvt7_kernel(
    const float* __restrict__ i0, const float* __restrict__ i1,
    const float* __restrict__ i2, const float* __restrict__ i3,
    const float* __restrict__ i4, const float* __restrict__ i5,
    const float* __restrict__ i6,
    __half* __restrict__ o0, __half* __restrict__ o1,
    __half* __restrict__ o2, __half* __restrict__ o3,
    __half* __restrict__ o4, __half* __restrict__ o5,
    __half* __restrict__ o6,
    int n4x, int n4w)
{
    const int z = blockIdx.z;
    const int n4 = (z < 3) ? n4x : n4w;
    int i = blockIdx.x * blockDim.x + threadIdx.x;
    if (i >= n4) return;
    const float* in;
    __half* out;
    switch (z) {
        case 0: in = i0; out = o0; break;
        case 1: in = i1; out = o1; break;
        case 2: in = i2; out = o2; break;
        case 3: in = i3; out = o3; break;
        case 4: in = i4; out = o4; break;
        case 5: in = i5; out = o5; break;
        default: in = i6; out = o6; break;
    }
    float4 v = ((const float4*)in)[i];
    uint2 o;
    o.x = h2pack(v.x, v.y);
    o.y = h2pack(v.z, v.w);
    ((uint2*)out)[i] = o;
}

// ===========================================================================
// fp16 HMMA GEMM — R12 mainloop (measured best), .ca cp.async.
// Epilogue applies per-z output scale (folds attention scale*log2e into Q).
// ===========================================================================
#define GRS    40
#define GTILE  (128 * GRS * 2)
#define GSTAGE (2 * GTILE)
#define NSTG   3
#define GEMM_SMEM (NSTG * GSTAGE)       // 61440 B

__global__ __launch_bounds__(128, 2) void gemm_f16_kernel(
    const __half* __restrict__ A0, const __half* __restrict__ A1,
    const __half* __restrict__ A2,
    const __half* __restrict__ W0, const __half* __restrict__ W1,
    const __half* __restrict__ W2,
    const float* __restrict__ b0, const float* __restrict__ b1,
    const float* __restrict__ b2,
    float* __restrict__ Cf,
    __half* __restrict__ H0, __half* __restrict__ H1, __half* __restrict__ H2,
    int outhalf, float s0, float s1, float s2, int M, int N, int Kd)
{
    extern __shared__ char smem[];
    const uint32_t sbase = smem_u32(smem);
    const int z = blockIdx.z;
    const __half* Ah   = (z == 0) ? A0 : (z == 1) ? A1 : A2;
    const __half* Wh   = (z == 0) ? W0 : (z == 1) ? W1 : W2;
    const float*  bias = (z == 0) ? b0 : (z == 1) ? b1 : b2;
    __half*       Ch   = (z == 0) ? H0 : (z == 1) ? H1 : H2;
    const float   osc  = (z == 0) ? s0 : (z == 1) ? s1 : s2;

    const int tid  = threadIdx.x;
    const int wid  = tid >> 5;
    const int lane = tid & 31;
    const int wm   = wid >> 1;
    const int wn   = wid & 1;
    const int bm   = blockIdx.y * 128;
    const int bn   = blockIdx.x * 128;

    float acc[4][8][4];
    #pragma unroll
    for (int i = 0; i < 4; i++)
        #pragma unroll
        for (int j = 0; j < 8; j++)
            #pragma unroll
            for (int e = 0; e < 4; e++) acc[i][j][e] = 0.f;

    const int crow = tid >> 2;
    const int ccol = tid & 3;

#define ISSUE_STAGE(CH, STG) do {                                             \
    const int k0_ = (CH) * 32;                                                \
    const uint32_t sb_ = sbase + (STG) * GSTAGE;                              \
    _Pragma("unroll")                                                         \
    for (int t = 0; t < 4; t++) {                                             \
        const int row_ = crow + t * 32;                                       \
        const uint32_t so_ = (uint32_t)(row_ * 80 + ccol * 16);               \
        cp16(sb_ + so_,         Ah + (size_t)(bm + row_) * Kd + k0_ + ccol * 8); \
        cp16(sb_ + GTILE + so_, Wh + (size_t)(bn + row_) * Kd + k0_ + ccol * 8); \
    }                                                                         \
} while (0)

    #pragma unroll
    for (int s = 0; s < NSTG; s++) { ISSUE_STAGE(s, s); CP_COMMIT(); }

    const int g  = lane >> 3;
    const int r8 = lane & 7;
    const int nchunk = Kd / 32;

    for (int ch = 0; ch < nchunk; ch++) {
        CP_WAIT(NSTG - 1);
        __syncthreads();
        const uint32_t buf = sbase + (ch % NSTG) * GSTAGE;

        #pragma unroll
        for (int ks = 0; ks < 2; ks++) {
            const int k0 = ks * 16;
            uint32_t af[4][4];
            #pragma unroll
            for (int mt = 0; mt < 4; mt++) {
                int row = wm * 64 + mt * 16 + r8 + (g & 1) * 8;
                uint32_t off = (uint32_t)(row * GRS + k0 + (g >> 1) * 8) * 2;
                ldsm_x4(buf + off, af[mt]);
            }
            uint32_t bf[4][4];
            #pragma unroll
            for (int np = 0; np < 4; np++) {
                int nrow = wn * 64 + np * 16 + r8 + (g >> 1) * 8;
                uint32_t off = (uint32_t)(nrow * GRS + k0 + (g & 1) * 8) * 2;
                ldsm_x4(buf + GTILE + off, bf[np]);
            }
            #pragma unroll
            for (int mt = 0; mt < 4; mt++) {
                #pragma unroll
                for (int nt = 0; nt < 8; nt++) {
                    const int np = nt >> 1, hf = (nt & 1) * 2;
                    mma_f16(acc[mt][nt], af[mt], bf[np][hf], bf[np][hf + 1]);
                }
            }
        }
        __syncthreads();
        if (ch + NSTG < nchunk) ISSUE_STAGE(ch + NSTG, ch % NSTG);
        CP_COMMIT();
    }

    // Epilogue: (acc + bias) * osc.
    #pragma unroll
    for (int nt = 0; nt < 8; nt++) {
        const int gcol = bn + wn * 64 + nt * 8 + (lane & 3) * 2;
        const float2 bv = *(const float2*)&bias[gcol];
        #pragma unroll
        for (int mt = 0; mt < 4; mt++) {
            const int grow = bm + wm * 64 + mt * 16 + (lane >> 2);
            float x0 = (acc[mt][nt][0] + bv.x) * osc;
            float y0 = (acc[mt][nt][1] + bv.y) * osc;
            float x1 = (acc[mt][nt][2] + bv.x) * osc;
            float y1 = (acc[mt][nt][3] + bv.y) * osc;
            if (outhalf) {
                *(uint32_t*)&Ch[(size_t)grow * N + gcol] = h2pack(x0, y0);
                *(uint32_t*)&Ch[(size_t)(grow + 8) * N + gcol] = h2pack(x1, y1);
            } else {
                float2 o0 = {x0, y0}, o1 = {x1, y1};
                *(float2*)&Cf[(size_t)grow * N + gcol] = o0;
                *(float2*)&Cf[(size_t)(grow + 8) * N + gcol] = o1;
            }
        }
    }
#undef ISSUE_STAGE
}

// ===========================================================================
// Flash attention, fp16 HMMA, P-in-registers. Log2-domain softmax
// (Q pre-scaled by scale*log2e), warp-uniform causal mask, .ca cp.async.
// ===========================================================================
#define VRS     136
#define FT_TILE (64 * VRS * 2)
#define FSM_KV0 FT_TILE
#define FLASH_SMEM (FT_TILE * 5)        // 87040 B

__global__ __launch_bounds__(128, 1) void flash_hmma_kernel(
    const __half* __restrict__ Q, const __half* __restrict__ K,
    const __half* __restrict__ V, const int* __restrict__ causal_ptr,
    __half* __restrict__ O)
{
    extern __shared__ char smem[];
    const uint32_t sb = smem_u32(smem);
    const int tid  = threadIdx.x;
    const int lane = tid & 31;
    const int wq   = tid >> 5;
    const int qt   = blockIdx.x;
    const int h    = blockIdx.y;
    const int b    = blockIdx.z;
    const int q0   = qt * 64;
    const size_t base = (size_t)b * SEQ * DIM + (size_t)h * DH;
    const int causal = *causal_ptr;
    const int nkt = causal ? (qt + 1) : (SEQ / 64);

    const int g  = lane >> 3;
    const int r8 = lane & 7;
    const int r  = lane >> 2;
    const int cc = (lane & 3) * 2;

#define ISSUE_KV(KT, STG) do {                                                \
    const int kk0_ = (KT) * 64;                                               \
    const uint32_t tb_ = sb + FSM_KV0 + (STG) * 2 * FT_TILE;                  \
    _Pragma("unroll")                                                         \
    for (int t = 0; t < 8; t++) {                                             \
        int idx = tid + t * 128;                                              \
        int row = idx >> 4, c = idx & 15;                                     \
        cp16(tb_ + row * 272 + c * 16,                                        \
             K + base + (size_t)(kk0_ + row) * DIM + c * 8);                  \
        cp16(tb_ + FT_TILE + row * 272 + c * 16,                              \
             V + base + (size_t)(kk0_ + row) * DIM + c * 8);                  \
    }                                                                         \
} while (0)

    #pragma unroll
    for (int t = 0; t < 8; t++) {
        int idx = tid + t * 128;
        int row = idx >> 4, c = idx & 15;
        cp16(sb + row * 272 + c * 16,
             Q + base + (size_t)(q0 + row) * DIM + c * 8);
    }
    ISSUE_KV(0, 0);
    CP_COMMIT();
    ISSUE_KV((1 < nkt ? 1 : nkt - 1), 1);
    CP_COMMIT();

    float m0 = -INFINITY, m1 = -INFINITY, l0 = 0.f, l1 = 0.f;
    float o[16][4];
    #pragma unroll
    for (int u = 0; u < 16; u++)
        #pragma unroll
        for (int e = 0; e < 4; e++) o[u][e] = 0.f;

    uint32_t aq[8][4];

    for (int kt = 0; kt < nkt; kt++) {
        CP_WAIT(1);
        __syncthreads();

        if (kt == 0) {
            #pragma unroll
            for (int ds = 0; ds < 8; ds++) {
                uint32_t addr = sb + (uint32_t)(wq * 16 + r8 + (g & 1) * 8) * 272
                              + (uint32_t)(ds * 16 + (g >> 1) * 8) * 2;
                ldsm_x4(addr, aq[ds]);
            }
        }

        const uint32_t kbuf = sb + FSM_KV0 + (uint32_t)(kt & 1) * 2 * FT_TILE;
        const uint32_t vbuf = kbuf + FT_TILE;

        float c[8][4];
        #pragma unroll
        for (int nt = 0; nt < 8; nt++)
            #pragma unroll
            for (int e = 0; e < 4; e++) c[nt][e] = 0.f;

        #pragma unroll
        for (int ds = 0; ds < 8; ds++) {
            uint32_t bf[4][4];
            #pragma unroll
            for (int j = 0; j < 4; j++) {
                uint32_t addr = kbuf + (uint32_t)(j * 16 + r8 + (g >> 1) * 8) * 272
                              + (uint32_t)(ds * 16 + (g & 1) * 8) * 2;
                ldsm_x4(addr, bf[j]);
            }
            #pragma unroll
            for (int nt = 0; nt < 8; nt++)
                mma_f16(c[nt], aq[ds], bf[nt >> 1][(nt & 1) * 2],
                        bf[nt >> 1][(nt & 1) * 2 + 1]);
        }

        // Causal mask, warp-uniform branch (scale pre-folded into Q).
        if (causal && (kt == qt)) {
            const int qrow0 = q0 + wq * 16 + r;
            #pragma unroll
            for (int nt = 0; nt < 8; nt++) {
                #pragma unroll
                for (int e = 0; e < 4; e++) {
                    int key = kt * 64 + nt * 8 + cc + (e & 1);
                    int qr  = qrow0 + ((e >> 1) << 3);
                    if (key > qr) c[nt][e] = -INFINITY;
                }
            }
        }

        float mx0 = -INFINITY, mx1 = -INFINITY;
        #pragma unroll
        for (int nt = 0; nt < 8; nt++) {
            mx0 = fmaxf(mx0, fmaxf(c[nt][0], c[nt][1]));
            mx1 = fmaxf(mx1, fmaxf(c[nt][2], c[nt][3]));
        }
        mx0 = fmaxf(mx0, __shfl_xor_sync(0xffffffffu, mx0, 1));
        mx0 = fmaxf(mx0, __shfl_xor_sync(0xffffffffu, mx0, 2));
        mx1 = fmaxf(mx1, __shfl_xor_sync(0xffffffffu, mx1, 1));
        mx1 = fmaxf(mx1, __shfl_xor_sync(0xffffffffu, mx1, 2));
        const float nm0 = fmaxf(m0, mx0), nm1 = fmaxf(m1, mx1);
        const float cor0 = exp2f(m0 - nm0), cor1 = exp2f(m1 - nm1);

        uint32_t ph[8][2];
        float rs0 = 0.f, rs1 = 0.f;
        #pragma unroll
        for (int nt = 0; nt < 8; nt++) {
            float p0 = exp2f(c[nt][0] - nm0);
            float p1 = exp2f(c[nt][1] - nm0);
            float p2 = exp2f(c[nt][2] - nm1);
            float p3 = exp2f(c[nt][3] - nm1);
            rs0 += p0 + p1; rs1 += p2 + p3;
            ph[nt][0] = h2pack(p0, p1);
            ph[nt][1] = h2pack(p2, p3);
        }
        rs0 += __shfl_xor_sync(0xffffffffu, rs0, 1);
        rs0 += __shfl_xor_sync(0xffffffffu, rs0, 2);
        rs1 += __shfl_xor_sync(0xffffffffu, rs1, 1);
        rs1 += __shfl_xor_sync(0xffffffffu, rs1, 2);
        l0 = l0 * cor0 + rs0;
        l1 = l1 * cor1 + rs1;
        m0 = nm0; m1 = nm1;

        #pragma unroll
        for (int u = 0; u < 16; u++) {
            o[u][0] *= cor0; o[u][1] *= cor0;
            o[u][2] *= cor1; o[u][3] *= cor1;
        }

        #pragma unroll
        for (int kk = 0; kk < 4; kk++) {
            uint32_t pa[4] = { ph[2 * kk][0], ph[2 * kk][1],
                               ph[2 * kk + 1][0], ph[2 * kk + 1][1] };
            #pragma unroll
            for (int u = 0; u < 8; u++) {
                uint32_t bv[4];
                uint32_t addr = vbuf + (uint32_t)(kk * 16 + (lane & 15)) * 272
                              + (uint32_t)(u * 16 + (lane >> 4) * 8) * 2;
                ldsm_x4_t(addr, bv);
                mma_f16(o[2 * u],     pa, bv[0], bv[1]);
                mma_f16(o[2 * u + 1], pa, bv[2], bv[3]);
            }
        }

        __syncthreads();
        {
            int nx = kt + 2;
            if (nx >= nkt) nx = nkt - 1;
            ISSUE_KV(nx, kt & 1);
        }
        CP_COMMIT();
    }

    const float inv0 = 1.f / l0, inv1 = 1.f / l1;
    const int row0 = q0 + wq * 16 + r;
    #pragma unroll
    for (int u = 0; u < 16; u++) {
        int col = u * 8 + cc;
        *(uint32_t*)&O[base + (size_t)row0 * DIM + col] =
            h2pack(o[u][0] * inv0, o[u][1] * inv0);
        *(uint32_t*)&O[base + (size_t)(row0 + 8) * DIM + col] =
            h2pack(o[u][2] * inv1, o[u][3] * inv1);
    }
#undef ISSUE_KV
}

// ===========================================================================
extern "C" void kernel_launch(void* const* d_in, const int* in_sizes, int n_in,
                              void* d_out, int out_size)
{
    const float* q      = (const float*)d_in[0];
    const float* k      = (const float*)d_in[1];
    const float* v      = (const float*)d_in[2];
    const float* Wq     = (const float*)d_in[3];
    const float* bq     = (const float*)d_in[4];
    const float* Wk     = (const float*)d_in[5];
    const float* bk     = (const float*)d_in[6];
    const float* Wv     = (const float*)d_in[7];
    const float* bv     = (const float*)d_in[8];
    const float* Wo     = (const float*)d_in[9];
    const float* bo     = (const float*)d_in[10];
    const int*   causal = (const int*)d_in[11];
    float* out = (float*)d_out;

    __half *hI0, *hI1, *hI2, *hQ, *hK, *hV, *hO, *hW0, *hW1, *hW2, *hW3;
    cudaGetSymbolAddress((void**)&hI0, g_hI0);
    cudaGetSymbolAddress((void**)&hI1, g_hI1);
    cudaGetSymbolAddress((void**)&hI2, g_hI2);
    cudaGetSymbolAddress((void**)&hQ,  g_hQ);
    cudaGetSymbolAddress((void**)&hK,  g_hK);
    cudaGetSymbolAddress((void**)&hV,  g_hV);
    cudaGetSymbolAddress((void**)&hO,  g_hO);
    cudaGetSymbolAddress((void**)&hW0, g_hW0);
    cudaGetSymbolAddress((void**)&hW1, g_hW1);
    cudaGetSymbolAddress((void**)&hW2, g_hW2);
    cudaGetSymbolAddress((void**)&hW3, g_hW3);

    const int M = BATCH * SEQ;                   // 4096
    const int n4x = M * DIM / 4;
    const int n4w = DIM * DIM / 4;

    cudaFuncSetAttribute(gemm_f16_kernel,
                         cudaFuncAttributeMaxDynamicSharedMemorySize, GEMM_SMEM);
    cudaFuncSetAttribute(flash_hmma_kernel,
                         cudaFuncAttributeMaxDynamicSharedMemorySize, FLASH_SMEM);

    // All seven fp32->fp16 conversions in one launch.
    {
        dim3 cg(n4x / 256, 1, 7);
        cvt7_kernel<<<cg, 256>>>(q, k, v, Wq, Wk, Wv, Wo,
                                 hI0, hI1, hI2, hW0, hW1, hW2, hW3,
                                 n4x, n4w);
    }

    // Three projections in one launch; Q output pre-scaled by scale*log2e.
    {
        dim3 gg(DIM / 128, M / 128, 3);
        gemm_f16_kernel<<<gg, 128, GEMM_SMEM>>>(
            hI0, hI1, hI2, hW0, hW1, hW2, bq, bk, bv,
            nullptr, hQ, hK, hV, 1, QSCALE, 1.0f, 1.0f, M, DIM, DIM);
    }

    // Attention (log2-domain softmax).
    {
        dim3 fg(SEQ / 64, NH, BATCH);
        flash_hmma_kernel<<<fg, 128, FLASH_SMEM>>>(hQ, hK, hV, causal, hO);
    }

    // Output projection (fp32 out, unit scale).
    {
        dim3 gg(DIM / 128, M / 128, 1);
        gemm_f16_kernel<<<gg, 128, GEMM_SMEM>>>(
            hO, hO, hO, hW3, hW3, hW3, bo, bo, bo,
            out, nullptr, nullptr, nullptr, 0, 1.0f, 1.0f, 1.0f, M, DIM, DIM);
    }
}